// round 1
// baseline (speedup 1.0000x reference)
#include <cuda_runtime.h>
#include <math.h>

#define B 64
#define C 256
#define H 56
#define W 56
#define HW 3136
#define HW4 784          // HW / 4
#define D 16
#define TOPK 38
#define HALF 2
#define NROWS (B * C)    // 16384
#define NSEL (B * TOPK)  // 2432

// Scratch (device globals — no allocation allowed)
__device__ float g_pooled[NROWS];
__device__ int   g_amax[NROWS];
__device__ int   g_sel[NSEL];

// ---------------------------------------------------------------------------
// Kernel 1: per-(b,c) plane — copy x -> out, compute mean and argmax.
// One block (256 threads) per row of 3136 floats (784 float4).
// ---------------------------------------------------------------------------
__global__ __launch_bounds__(256) void k1_pool_amax_copy(
    const float4* __restrict__ x, float4* __restrict__ out)
{
    const int row = blockIdx.x;
    const float4* __restrict__ xr = x + (size_t)row * HW4;
    float4* __restrict__ orow = out + (size_t)row * HW4;
    const int t = threadIdx.x;

    float s = 0.0f;
    float bv = -INFINITY;
    int   bi = 0x7FFFFFFF;

    #pragma unroll 4
    for (int i = t; i < HW4; i += 256) {
        float4 v = xr[i];
        orow[i] = v;
        s += (v.x + v.y) + (v.z + v.w);
        int base = i << 2;
        // strict > keeps first occurrence within this thread's ascending indices
        if (v.x > bv) { bv = v.x; bi = base; }
        if (v.y > bv) { bv = v.y; bi = base + 1; }
        if (v.z > bv) { bv = v.z; bi = base + 2; }
        if (v.w > bv) { bv = v.w; bi = base + 3; }
    }

    // warp reduce: sum + (max val, min idx on tie)
    #pragma unroll
    for (int o = 16; o > 0; o >>= 1) {
        float ov = __shfl_down_sync(0xFFFFFFFFu, bv, o);
        int   oi = __shfl_down_sync(0xFFFFFFFFu, bi, o);
        float os = __shfl_down_sync(0xFFFFFFFFu, s, o);
        s += os;
        if (ov > bv || (ov == bv && oi < bi)) { bv = ov; bi = oi; }
    }

    __shared__ float sv[8], ss[8];
    __shared__ int   si[8];
    const int w = t >> 5, l = t & 31;
    if (l == 0) { sv[w] = bv; si[w] = bi; ss[w] = s; }
    __syncthreads();
    if (t == 0) {
        float fbv = sv[0]; int fbi = si[0]; float fs = ss[0];
        #pragma unroll
        for (int j = 1; j < 8; j++) {
            fs += ss[j];
            if (sv[j] > fbv || (sv[j] == fbv && si[j] < fbi)) { fbv = sv[j]; fbi = si[j]; }
        }
        g_pooled[row] = fs * (1.0f / (float)HW);
        g_amax[row]   = fbi;
    }
}

// ---------------------------------------------------------------------------
// Kernel 2: SE module (two tiny matmuls + sigmoid) + top-38 selection.
// One block per batch sample b, 256 threads = channels.
// Deterministic compaction: rank r in [0,38) writes g_sel[b*38 + r].
// ---------------------------------------------------------------------------
__global__ __launch_bounds__(256) void k2_se_topk(
    const float* __restrict__ w1, const float* __restrict__ w2)
{
    const int b = blockIdx.x;
    const int c = threadIdx.x;
    __shared__ float p[C];
    __shared__ float h[D];
    __shared__ float m[C];

    p[c] = g_pooled[b * C + c];
    __syncthreads();

    if (c < D) {
        float a = 0.0f;
        const float* w1r = w1 + c * C;
        #pragma unroll 8
        for (int j = 0; j < C; j++) a = fmaf(p[j], w1r[j], a);
        h[c] = fmaxf(a, 0.0f);
    }
    __syncthreads();

    float z = 0.0f;
    const float* w2r = w2 + c * D;
    #pragma unroll
    for (int d = 0; d < D; d++) z = fmaf(h[d], w2r[d], z);
    m[c] = 1.0f / (1.0f + expf(-z));
    __syncthreads();

    const float mc = m[c];
    int rank = 0;
    #pragma unroll 8
    for (int j = 0; j < C; j++) {
        float mj = m[j];
        rank += (mj > mc) || (mj == mc && j < c);
    }
    if (rank < TOPK) g_sel[b * TOPK + rank] = b * C + c;
}

// ---------------------------------------------------------------------------
// Kernel 3: rewrite only the 2432 selected rows with the drop-box mask.
// One block per selected row.
// ---------------------------------------------------------------------------
__global__ __launch_bounds__(256) void k3_apply(
    const float4* __restrict__ x, float4* __restrict__ out)
{
    const int row = g_sel[blockIdx.x];
    const int mi = g_amax[row];
    const int mh = mi / W, mw = mi % W;
    const int h1 = max(mh - HALF, 0), h2 = min(mh + HALF, H - 1);
    const int wl = max(mw - HALF, 0), wr = min(mw + HALF, W - 1);
    const float lam = (float)HW / ((float)HW - (float)((h2 - h1 + 1) * (wr - wl + 1)));

    const float4* __restrict__ xr = x + (size_t)row * HW4;
    float4* __restrict__ orow = out + (size_t)row * HW4;

    for (int i = threadIdx.x; i < HW4; i += 256) {
        float4 v = xr[i];
        const int e = i << 2;
        const int hh = e / W;         // W % 4 == 0: all 4 lanes share this h
        const int ww = e - hh * W;
        const bool hin = (hh >= h1) & (hh <= h2);
        float4 r;
        r.x = (hin & (ww     >= wl) & (ww     <= wr)) ? 0.0f : v.x * lam;
        r.y = (hin & (ww + 1 >= wl) & (ww + 1 <= wr)) ? 0.0f : v.y * lam;
        r.z = (hin & (ww + 2 >= wl) & (ww + 2 <= wr)) ? 0.0f : v.z * lam;
        r.w = (hin & (ww + 3 >= wl) & (ww + 3 <= wr)) ? 0.0f : v.w * lam;
        orow[i] = r;
    }
}

// ---------------------------------------------------------------------------
extern "C" void kernel_launch(void* const* d_in, const int* in_sizes, int n_in,
                              void* d_out, int out_size)
{
    const float4* x  = (const float4*)d_in[0];
    const float*  w1 = (const float*)d_in[1];
    const float*  w2 = (const float*)d_in[2];
    float4* out = (float4*)d_out;

    k1_pool_amax_copy<<<NROWS, 256>>>(x, out);
    k2_se_topk<<<B, 256>>>(w1, w2);
    k3_apply<<<NSEL, 256>>>(x, out);
}

// round 3
// speedup vs baseline: 1.1816x; 1.1816x over previous
#include <cuda_runtime.h>
#include <math.h>

#define B 64
#define C 256
#define H 56
#define W 56
#define HW 3136
#define HW4 784          // HW / 4
#define D 16
#define TOPK 38
#define HALF 2
#define NROWS (B * C)    // 16384
#define NSEL (B * TOPK)  // 2432

// Scratch (device globals — no allocation allowed)
__device__ float g_pooled[NROWS];
__device__ int   g_amax[NROWS];
__device__ int   g_sel[NSEL];   // packed: (row << 12) | argmax_idx

// ---------------------------------------------------------------------------
// Kernel 1: per-(b,c) plane — copy x -> out (evict-first stores),
// compute mean and argmax. One block (256 threads) per row (784 float4).
// 784 = 3*256 + 16: every thread handles 3 float4, threads 0..15 a 4th.
// Loads batched up-front for MLP; stores + reduction after.
// ---------------------------------------------------------------------------
__global__ __launch_bounds__(256) void k1_pool_amax_copy(
    const float4* __restrict__ x, float4* __restrict__ out)
{
    const int row = blockIdx.x;
    const float4* __restrict__ xr = x + (size_t)row * HW4;
    float4* __restrict__ orow = out + (size_t)row * HW4;
    const int t = threadIdx.x;
    const bool tail = (t < 16);

    // Batch all loads first (MLP = 3-4)
    float4 v0 = xr[t];
    float4 v1 = xr[t + 256];
    float4 v2 = xr[t + 512];
    float4 v3;
    if (tail) v3 = xr[t + 768];

    // Streaming stores (out is write-only from L2's perspective)
    __stcs(orow + t,       v0);
    __stcs(orow + t + 256, v1);
    __stcs(orow + t + 512, v2);
    if (tail) __stcs(orow + t + 768, v3);

    // Sum
    float s = ((v0.x + v0.y) + (v0.z + v0.w))
            + ((v1.x + v1.y) + (v1.z + v1.w))
            + ((v2.x + v2.y) + (v2.z + v2.w));
    if (tail) s += ((v3.x + v3.y) + (v3.z + v3.w));

    // Argmax (first-index tie-break: ascending index order, strict >)
    float bv = v0.x; int bi = (t << 2);
    if (v0.y > bv) { bv = v0.y; bi = (t << 2) + 1; }
    if (v0.z > bv) { bv = v0.z; bi = (t << 2) + 2; }
    if (v0.w > bv) { bv = v0.w; bi = (t << 2) + 3; }
    {
        const int b1 = ((t + 256) << 2);
        if (v1.x > bv) { bv = v1.x; bi = b1; }
        if (v1.y > bv) { bv = v1.y; bi = b1 + 1; }
        if (v1.z > bv) { bv = v1.z; bi = b1 + 2; }
        if (v1.w > bv) { bv = v1.w; bi = b1 + 3; }
        const int b2 = ((t + 512) << 2);
        if (v2.x > bv) { bv = v2.x; bi = b2; }
        if (v2.y > bv) { bv = v2.y; bi = b2 + 1; }
        if (v2.z > bv) { bv = v2.z; bi = b2 + 2; }
        if (v2.w > bv) { bv = v2.w; bi = b2 + 3; }
    }
    if (tail) {
        const int b3 = ((t + 768) << 2);
        if (v3.x > bv) { bv = v3.x; bi = b3; }
        if (v3.y > bv) { bv = v3.y; bi = b3 + 1; }
        if (v3.z > bv) { bv = v3.z; bi = b3 + 2; }
        if (v3.w > bv) { bv = v3.w; bi = b3 + 3; }
    }

    // Warp reduce: sum + (max val, min idx on tie)
    #pragma unroll
    for (int o = 16; o > 0; o >>= 1) {
        float ov = __shfl_down_sync(0xFFFFFFFFu, bv, o);
        int   oi = __shfl_down_sync(0xFFFFFFFFu, bi, o);
        float os = __shfl_down_sync(0xFFFFFFFFu, s,  o);
        s += os;
        if (ov > bv || (ov == bv && oi < bi)) { bv = ov; bi = oi; }
    }

    __shared__ float sv[8], ss[8];
    __shared__ int   si[8];
    const int w = t >> 5, l = t & 31;
    if (l == 0) { sv[w] = bv; si[w] = bi; ss[w] = s; }
    __syncthreads();
    if (t == 0) {
        float fbv = sv[0]; int fbi = si[0]; float fs = ss[0];
        #pragma unroll
        for (int j = 1; j < 8; j++) {
            fs += ss[j];
            if (sv[j] > fbv || (sv[j] == fbv && si[j] < fbi)) { fbv = sv[j]; fbi = si[j]; }
        }
        g_pooled[row] = fs * (1.0f / (float)HW);
        g_amax[row]   = fbi;
    }
}

// ---------------------------------------------------------------------------
// Kernel 2: SE (two tiny matmuls + sigmoid) + top-38 selection.
// One block per batch sample, 256 threads. w1 staged via smem cooperatively.
// Writes packed (row<<12 | argmax) so k3 has a single dependent load.
// ---------------------------------------------------------------------------
__global__ __launch_bounds__(256) void k2_se_topk(
    const float* __restrict__ w1, const float* __restrict__ w2)
{
    const int b = blockIdx.x;
    const int c = threadIdx.x;
    __shared__ float p[C];
    __shared__ float w1s[D * C];  // 16 KB
    __shared__ float h[D];
    __shared__ float m[C];

    p[c] = g_pooled[b * C + c];
    // Cooperative coalesced stage of w1 (4096 floats = 1024 float4)
    {
        const float4* w1v = (const float4*)w1;
        float4* w1sv = (float4*)w1s;
        #pragma unroll
        for (int i = 0; i < 4; i++) w1sv[c + i * 256] = w1v[c + i * 256];
    }
    __syncthreads();

    // hidden[d] with 16 threads per d (d = c>>4), 16-lane shfl segment reduce
    {
        const int d = c >> 4, g = c & 15;
        float a = 0.0f;
        #pragma unroll
        for (int j = 0; j < 16; j++) {
            const int cc = g * 16 + j;
            a = fmaf(p[cc], w1s[d * C + cc], a);
        }
        #pragma unroll
        for (int o = 8; o > 0; o >>= 1) a += __shfl_xor_sync(0xFFFFFFFFu, a, o);
        if (g == 0) h[d] = fmaxf(a, 0.0f);
    }
    __syncthreads();

    float z = 0.0f;
    const float* w2r = w2 + c * D;
    #pragma unroll
    for (int d = 0; d < D; d++) z = fmaf(h[d], w2r[d], z);
    m[c] = 1.0f / (1.0f + expf(-z));
    __syncthreads();

    // Rank within sample: deterministic compaction into g_sel
    const float mc = m[c];
    int rank = 0;
    #pragma unroll 8
    for (int j = 0; j < C; j++) {
        const float mj = m[j];
        rank += (mj > mc) || (mj == mc && j < c);
    }
    if (rank < TOPK) {
        const int row = b * C + c;
        const int mi = g_amax[row];          // 12 bits (HW=3136)
        g_sel[b * TOPK + rank] = (row << 12) | mi;
    }
}

// ---------------------------------------------------------------------------
// Kernel 3: rewrite only the 2432 selected rows with the drop-box mask.
// One block per selected row; single dependent load for (row, argmax).
// ---------------------------------------------------------------------------
__global__ __launch_bounds__(256) void k3_apply(
    const float4* __restrict__ x, float4* __restrict__ out)
{
    const int packed = g_sel[blockIdx.x];
    const int row = packed >> 12;
    const int mi  = packed & 0xFFF;
    const int mh = mi / W, mw = mi % W;
    const int h1 = max(mh - HALF, 0), h2 = min(mh + HALF, H - 1);
    const int wl = max(mw - HALF, 0), wr = min(mw + HALF, W - 1);
    const float lam = (float)HW / ((float)HW - (float)((h2 - h1 + 1) * (wr - wl + 1)));

    const float4* __restrict__ xr = x + (size_t)row * HW4;
    float4* __restrict__ orow = out + (size_t)row * HW4;
    const int t = threadIdx.x;
    const bool tail = (t < 16);

    float4 v0 = xr[t];
    float4 v1 = xr[t + 256];
    float4 v2 = xr[t + 512];
    float4 v3;
    if (tail) v3 = xr[t + 768];

    #define APPLY(v, i4) {                                              \
        const int e  = (i4) << 2;                                       \
        const int hh = e / W;                                           \
        const int ww = e - hh * W;                                      \
        const bool hin = (hh >= h1) & (hh <= h2);                       \
        float4 r;                                                       \
        r.x = (hin & (ww     >= wl) & (ww     <= wr)) ? 0.0f : v.x * lam; \
        r.y = (hin & (ww + 1 >= wl) & (ww + 1 <= wr)) ? 0.0f : v.y * lam; \
        r.z = (hin & (ww + 2 >= wl) & (ww + 2 <= wr)) ? 0.0f : v.z * lam; \
        r.w = (hin & (ww + 3 >= wl) & (ww + 3 <= wr)) ? 0.0f : v.w * lam; \
        __stcs(orow + (i4), r);                                         \
    }

    APPLY(v0, t);
    APPLY(v1, t + 256);
    APPLY(v2, t + 512);
    if (tail) APPLY(v3, t + 768);
    #undef APPLY
}

// ---------------------------------------------------------------------------
extern "C" void kernel_launch(void* const* d_in, const int* in_sizes, int n_in,
                              void* d_out, int out_size)
{
    const float4* x  = (const float4*)d_in[0];
    const float*  w1 = (const float*)d_in[1];
    const float*  w2 = (const float*)d_in[2];
    float4* out = (float4*)d_out;

    k1_pool_amax_copy<<<NROWS, 256>>>(x, out);
    k2_se_topk<<<B, 256>>>(w1, w2);
    k3_apply<<<NSEL, 256>>>(x, out);
}